// round 1
// baseline (speedup 1.0000x reference)
#include <cuda_runtime.h>
#include <cstdint>

#define B 32
#define S 1024
#define D 512
#define TWOD 1024
#define VFULL 50000
#define NV 49000
#define BN_EPS 1e-5f

// ---------------- scratch (device globals; no allocation) ----------------
__device__ float g_dec_op1[B * TWOD];       // [B,2D]
__device__ float g_attn_logits[B * S];      // [B,S]
__device__ float g_context[B * TWOD];       // raw context accumulator
__device__ float g_hidden[B * D];           // [B,D]
__device__ float g_pgen[B];
__device__ float g_logits[B * NV];          // [B,NV]  ~6.3MB

__device__ __forceinline__ float tanh_fast(float x) {
    float y;
    asm("tanh.approx.f32 %0, %1;" : "=f"(y) : "f"(x));
    return y;
}

// ---------------- k1: dec_op1 = [h;c] @ W_dec^T + b_dec ----------------
// warp per output element (32768 outputs), grid 4096 x 256
__global__ void k1_decop1(const float* __restrict__ h, const float* __restrict__ c,
                          const float* __restrict__ W, const float* __restrict__ bias,
                          float* __restrict__ out) {
    int gw = (blockIdx.x * blockDim.x + threadIdx.x) >> 5;
    int lane = threadIdx.x & 31;
    int b = gw >> 10, j = gw & 1023;
    const float* wr = W + (size_t)j * TWOD;
    float acc = 0.f;
#pragma unroll 8
    for (int k = lane; k < TWOD; k += 32) {
        float x = (k < D) ? h[b * D + k] : c[b * D + k - D];
        acc += x * wr[k];
    }
#pragma unroll
    for (int o = 16; o; o >>= 1) acc += __shfl_xor_sync(0xffffffffu, acc, o);
    if (!lane) out[gw] = acc + bias[j];
}

// ---------------- k2: attn logits = tanh(enc_op1 + dec_op1) . w_attn ----------------
// grid (S/8, B), 256 threads (8 warps, warp per s-row)
__global__ void k2_attnlogits(const float* __restrict__ enc1, const float* __restrict__ dec1,
                              const float* __restrict__ wat, float* __restrict__ lg) {
    __shared__ float sd[TWOD];
    __shared__ float sw[TWOD];
    int b = blockIdx.y;
    for (int i = threadIdx.x; i < TWOD; i += 256) {
        sd[i] = dec1[b * TWOD + i];
        sw[i] = wat[i];
    }
    __syncthreads();
    int warp = threadIdx.x >> 5, lane = threadIdx.x & 31;
    int s = blockIdx.x * 8 + warp;
    const float4* e4 = (const float4*)(enc1 + ((size_t)(b * S + s)) * TWOD);
    const float4* sd4 = (const float4*)sd;
    const float4* sw4 = (const float4*)sw;
    float acc = 0.f;
#pragma unroll
    for (int i = 0; i < 8; i++) {
        int idx = lane + 32 * i;
        float4 e = e4[idx];
        float4 dv = sd4[idx];
        float4 wv = sw4[idx];
        acc += tanh_fast(e.x + dv.x) * wv.x;
        acc += tanh_fast(e.y + dv.y) * wv.y;
        acc += tanh_fast(e.z + dv.z) * wv.z;
        acc += tanh_fast(e.w + dv.w) * wv.w;
    }
#pragma unroll
    for (int o = 16; o; o >>= 1) acc += __shfl_xor_sync(0xffffffffu, acc, o);
    if (!lane) lg[b * S + s] = acc;
}

// ---------------- k3: masked softmax over S -> attn (also zero context acc) ----------------
// grid B, block 1024
__global__ void k3_softmax_attn(const float* __restrict__ lg, const int* __restrict__ src,
                                float* __restrict__ attn, float* __restrict__ ctx0) {
    __shared__ float red[1024];
    int b = blockIdx.x, t = threadIdx.x;
    ctx0[b * TWOD + t] = 0.f;   // zero context accumulator (same 32x1024 extent)
    float l = lg[b * S + t];
    red[t] = l; __syncthreads();
    for (int o = 512; o; o >>= 1) { if (t < o) red[t] = fmaxf(red[t], red[t + o]); __syncthreads(); }
    float m = red[0]; __syncthreads();
    float e = __expf(l - m);
    float me = (src[b * S + t] != 0) ? e : 0.f;
    red[t] = me; __syncthreads();
    for (int o = 512; o; o >>= 1) { if (t < o) red[t] += red[t + o]; __syncthreads(); }
    attn[b * S + t] = me / red[0];
}

// ---------------- k4: context = attn @ enc_op (split-s, atomic) ----------------
// grid (2D/256=4, B, S/256=4), 256 threads
__global__ void k4_context(const float* __restrict__ attn, const float* __restrict__ enc,
                           float* __restrict__ ctx) {
    __shared__ float sa[256];
    int b = blockIdx.y;
    int s0 = blockIdx.z * 256;
    int d = blockIdx.x * 256 + threadIdx.x;
    sa[threadIdx.x] = attn[b * S + s0 + threadIdx.x];
    __syncthreads();
    const float* ep = enc + ((size_t)(b * S + s0)) * TWOD + d;
    float acc = 0.f;
#pragma unroll 8
    for (int s = 0; s < 256; s++) acc += sa[s] * ep[(size_t)s * TWOD];
    atomicAdd(&ctx[b * TWOD + d], acc);
}

// ---------------- k5a: batchnorm -> context output ----------------
__global__ void k5_bn(const float* __restrict__ ctx, const float* __restrict__ gmean,
                      const float* __restrict__ gvar, const float* __restrict__ gamma,
                      const float* __restrict__ beta, float* __restrict__ ctxn) {
    int i = blockIdx.x * 256 + threadIdx.x;
    int j = i & 1023;
    ctxn[i] = (ctx[i] - gmean[j]) * rsqrtf(gvar[j] + BN_EPS) * gamma[j] + beta[j];
}

// ---------------- k5b: p_gen = sigmoid([ctxn; h; c; dec_inp] . W_p + b_p) ----------------
// grid B, 256 threads
__global__ void k5_pgen(const float* __restrict__ ctxn, const float* __restrict__ h,
                        const float* __restrict__ c, const float* __restrict__ dinp,
                        const float* __restrict__ Wp, const float* __restrict__ bp,
                        float* __restrict__ pg) {
    __shared__ float red[256];
    int b = blockIdx.x, t = threadIdx.x;
    float acc = 0.f;
    for (int k = t; k < 5 * D; k += 256) {
        float x;
        if (k < 1024)       x = ctxn[b * TWOD + k];
        else if (k < 1536)  x = h[b * D + k - 1024];
        else if (k < 2048)  x = c[b * D + k - 1536];
        else                x = dinp[b * D + k - 2048];
        acc += Wp[k] * x;
    }
    red[t] = acc; __syncthreads();
    for (int o = 128; o; o >>= 1) { if (t < o) red[t] += red[t + o]; __syncthreads(); }
    if (!t) pg[b] = 1.f / (1.f + __expf(-(red[0] + bp[0])));
}

// ---------------- k5c: hidden = [dec_output; ctxn] @ W_v1^T + b_v1 ----------------
// warp per output (16384 outputs), grid 2048 x 256
__global__ void k5_hidden(const float* __restrict__ dec_out, const float* __restrict__ ctxn,
                          const float* __restrict__ W1, const float* __restrict__ b1,
                          float* __restrict__ hid) {
    int gw = (blockIdx.x * blockDim.x + threadIdx.x) >> 5;
    int lane = threadIdx.x & 31;
    int b = gw >> 9, j = gw & 511;
    const float* wr = W1 + (size_t)j * (3 * D);
    float acc = 0.f;
#pragma unroll 8
    for (int k = lane; k < 3 * D; k += 32) {
        float x = (k < D) ? dec_out[b * D + k] : ctxn[b * TWOD + k - D];
        acc += x * wr[k];
    }
#pragma unroll
    for (int o = 16; o; o >>= 1) acc += __shfl_xor_sync(0xffffffffu, acc, o);
    if (!lane) hid[b * D + j] = acc + b1[j];
}

// ---------------- k6: logits = hidden @ W_v2^T + b_v2  (B=32 x NV=49000, K=512) ----------------
// block 256 threads, each thread owns one v-row and all 32 batch accumulators.
// hidden staged transposed in smem ([k][b], warp-broadcast LDS.128); W tiled through smem.
__global__ void k6_vocab(const float* __restrict__ hidden, const float* __restrict__ W2,
                         const float* __restrict__ b2, float* __restrict__ lg) {
    extern __shared__ float sm[];
    float* sh = sm;              // [512][32] -> sh[k*32+b]
    float* swt = sm + D * B;     // [256][17] W tile (pad 17 to dodge bank conflicts)
    int tid = threadIdx.x;
    for (int i = tid; i < D * B; i += 256) {
        int bb = i >> 9, k = i & 511;
        sh[k * 32 + bb] = hidden[i];
    }
    int v0 = blockIdx.x * 256;
    int v = v0 + tid;
    float acc[32];
#pragma unroll
    for (int b = 0; b < 32; b++) acc[b] = 0.f;
    float bias = (v < NV) ? b2[v] : 0.f;

    for (int kt = 0; kt < D; kt += 16) {
        __syncthreads();
        // load W tile: 256 rows x 16 cols, coalesced along k
#pragma unroll
        for (int j = 0; j < 16; j++) {
            int idx = j * 256 + tid;
            int r = idx >> 4, k = idx & 15;
            int vr = v0 + r;
            swt[r * 17 + k] = (vr < NV) ? W2[(size_t)vr * D + kt + k] : 0.f;
        }
        __syncthreads();
#pragma unroll
        for (int k = 0; k < 16; k++) {
            float w = swt[tid * 17 + k];
            const float4* h4 = (const float4*)&sh[(kt + k) * 32];
#pragma unroll
            for (int q = 0; q < 8; q++) {
                float4 hv = h4[q];
                acc[q * 4 + 0] += w * hv.x;
                acc[q * 4 + 1] += w * hv.y;
                acc[q * 4 + 2] += w * hv.z;
                acc[q * 4 + 3] += w * hv.w;
            }
        }
    }
    if (v < NV) {
#pragma unroll
        for (int b = 0; b < 32; b++) lg[(size_t)b * NV + v] = acc[b] + bias;
    }
}

// ---------------- k7: p_final[:, :NV] = p_gen * softmax(logits); tail zeros ----------------
// grid B, block 1024
__global__ void k7_pvocab(const float* __restrict__ lg, const float* __restrict__ pg,
                          float* __restrict__ pf) {
    __shared__ float red[1024];
    int b = blockIdx.x, t = threadIdx.x;
    const float* lr = lg + (size_t)b * NV;
    float m = -1e30f;
    for (int v = t; v < NV; v += 1024) m = fmaxf(m, lr[v]);
    red[t] = m; __syncthreads();
    for (int o = 512; o; o >>= 1) { if (t < o) red[t] = fmaxf(red[t], red[t + o]); __syncthreads(); }
    m = red[0]; __syncthreads();
    float s = 0.f;
    for (int v = t; v < NV; v += 1024) s += __expf(lr[v] - m);
    red[t] = s; __syncthreads();
    for (int o = 512; o; o >>= 1) { if (t < o) red[t] += red[t + o]; __syncthreads(); }
    float scale = pg[b] / red[0];
    float* pr = pf + (size_t)b * VFULL;
    for (int v = t; v < NV; v += 1024) pr[v] = scale * __expf(lr[v] - m);
    if (t < VFULL - NV) pr[NV + t] = 0.f;
}

// ---------------- k8: scatter-add (1-p_gen)*attn at src indices ----------------
__global__ void k8_scatter(const float* __restrict__ attn, const float* __restrict__ pg,
                           const int* __restrict__ src, float* __restrict__ pf) {
    int i = blockIdx.x * 256 + threadIdx.x;   // i in [0, B*S)
    int b = i >> 10;
    float w = (1.f - pg[b]) * attn[i];
    atomicAdd(&pf[(size_t)b * VFULL + src[i]], w);
}

// ---------------- k9: +1e-12 where exactly zero ----------------
__global__ void k9_eps(float* __restrict__ pf) {
    int i = blockIdx.x * 256 + threadIdx.x;   // i in [0, B*VFULL)
    float v = pf[i];
    if (v == 0.f) pf[i] = 1e-12f;
}

extern "C" void kernel_launch(void* const* d_in, const int* in_sizes, int n_in,
                              void* d_out, int out_size) {
    const float* dec_output = (const float*)d_in[0];
    const float* h          = (const float*)d_in[1];
    const float* c          = (const float*)d_in[2];
    const float* dec_inp    = (const float*)d_in[3];
    const float* enc_op     = (const float*)d_in[4];
    const float* enc_op1    = (const float*)d_in[5];
    const int*   src        = (const int*)d_in[6];
    const float* W_dec      = (const float*)d_in[7];
    const float* b_dec      = (const float*)d_in[8];
    const float* w_attn     = (const float*)d_in[9];
    const float* W_v1       = (const float*)d_in[10];
    const float* b_v1       = (const float*)d_in[11];
    const float* W_v2       = (const float*)d_in[12];
    const float* b_v2       = (const float*)d_in[13];
    const float* W_p        = (const float*)d_in[14];
    const float* b_p        = (const float*)d_in[15];
    const float* bn_gamma   = (const float*)d_in[16];
    const float* bn_beta    = (const float*)d_in[17];
    const float* bn_mean    = (const float*)d_in[18];
    const float* bn_var     = (const float*)d_in[19];

    float* out = (float*)d_out;
    float* pf       = out;                       // [B, VFULL]
    float* attn_out = out + (size_t)B * VFULL;   // [B, S]
    float* ctx_out  = attn_out + (size_t)B * S;  // [B, 2D]

    // device scratch symbols
    float *dec1, *alog, *ctx, *hid, *pg, *vlog;
    cudaGetSymbolAddress((void**)&dec1, g_dec_op1);
    cudaGetSymbolAddress((void**)&alog, g_attn_logits);
    cudaGetSymbolAddress((void**)&ctx,  g_context);
    cudaGetSymbolAddress((void**)&hid,  g_hidden);
    cudaGetSymbolAddress((void**)&pg,   g_pgen);
    cudaGetSymbolAddress((void**)&vlog, g_logits);

    static bool attr_done = false;
    if (!attr_done) {
        cudaFuncSetAttribute(k6_vocab, cudaFuncAttributeMaxDynamicSharedMemorySize,
                             (D * B + 256 * 17) * (int)sizeof(float));
        attr_done = true;
    }

    k1_decop1<<<(B * TWOD) / 8, 256>>>(h, c, W_dec, b_dec, dec1);
    k2_attnlogits<<<dim3(S / 8, B), 256>>>(enc_op1, dec1, w_attn, alog);
    k3_softmax_attn<<<B, 1024>>>(alog, src, attn_out, ctx);
    k4_context<<<dim3(TWOD / 256, B, S / 256), 256>>>(attn_out, enc_op, ctx);
    k5_bn<<<(B * TWOD) / 256, 256>>>(ctx, bn_mean, bn_var, bn_gamma, bn_beta, ctx_out);
    k5_pgen<<<B, 256>>>(ctx_out, h, c, dec_inp, W_p, b_p, pg);
    k5_hidden<<<(B * D) / 8, 256>>>(dec_output, ctx_out, W_v1, b_v1, hid);
    k6_vocab<<<(NV + 255) / 256, 256, (D * B + 256 * 17) * (int)sizeof(float)>>>(hid, W_v2, b_v2, vlog);
    k7_pvocab<<<B, 1024>>>(vlog, pg, pf);
    k8_scatter<<<(B * S) / 256, 256>>>(attn_out, pg, src, pf);
    k9_eps<<<(B * VFULL) / 256, 256>>>(pf);
}

// round 3
// speedup vs baseline: 1.0618x; 1.0618x over previous
#include <cuda_runtime.h>
#include <cstdint>

#define B 32
#define S 1024
#define D 512
#define TWOD 1024
#define VFULL 50000
#define NV 49000
#define BN_EPS 1e-5f
#define NCHUNK 48

// ---------------- scratch (device globals; no allocation) ----------------
__device__ float g_dec_op1[B * TWOD];
__device__ float g_attn_logits[B * S];
__device__ float g_context[B * TWOD];
__device__ float g_hidden[B * D];
__device__ float g_pgen[B];
__device__ float g_logits[B * NV];
__device__ float g_pmax[B * NCHUNK];
__device__ float g_psum[B * NCHUNK];
__device__ float g_scale[B];
__device__ float g_gmax[B];

__device__ __forceinline__ float tanh_fast(float x) {
    float y;
    asm("tanh.approx.f32 %0, %1;" : "=f"(y) : "f"(x));
    return y;
}

#define FMA2(acc, a, bb) asm("fma.rn.f32x2 %0, %1, %2, %0;" : "+l"(acc) : "l"(a), "l"(bb))
#define DUP2(out, x)     asm("mov.b64 %0, {%1, %1};" : "=l"(out) : "f"(x))
#define UNPK2(lo, hi, in) asm("mov.b64 {%0, %1}, %2;" : "=f"(lo), "=f"(hi) : "l"(in))

// ---------------- k1: dec_op1 = [h;c] @ W_dec^T + b_dec ----------------
__global__ void k1_decop1(const float* __restrict__ h, const float* __restrict__ c,
                          const float* __restrict__ W, const float* __restrict__ bias,
                          float* __restrict__ out) {
    int gw = (blockIdx.x * blockDim.x + threadIdx.x) >> 5;
    int lane = threadIdx.x & 31;
    int b = gw >> 10, j = gw & 1023;
    const float* wr = W + (size_t)j * TWOD;
    float acc = 0.f;
#pragma unroll 8
    for (int k = lane; k < TWOD; k += 32) {
        float x = (k < D) ? h[b * D + k] : c[b * D + k - D];
        acc += x * wr[k];
    }
#pragma unroll
    for (int o = 16; o; o >>= 1) acc += __shfl_xor_sync(0xffffffffu, acc, o);
    if (!lane) out[gw] = acc + bias[j];
}

// ---------------- k2: attn logits = tanh(enc_op1 + dec_op1) . w_attn ----------------
__global__ void k2_attnlogits(const float* __restrict__ enc1, const float* __restrict__ dec1,
                              const float* __restrict__ wat, float* __restrict__ lg) {
    __shared__ float sd[TWOD];
    __shared__ float sw[TWOD];
    int b = blockIdx.y;
    for (int i = threadIdx.x; i < TWOD; i += 256) {
        sd[i] = dec1[b * TWOD + i];
        sw[i] = wat[i];
    }
    __syncthreads();
    int warp = threadIdx.x >> 5, lane = threadIdx.x & 31;
    int s = blockIdx.x * 8 + warp;
    const float4* e4 = (const float4*)(enc1 + ((size_t)(b * S + s)) * TWOD);
    const float4* sd4 = (const float4*)sd;
    const float4* sw4 = (const float4*)sw;
    float acc = 0.f;
#pragma unroll
    for (int i = 0; i < 8; i++) {
        int idx = lane + 32 * i;
        float4 e = e4[idx];
        float4 dv = sd4[idx];
        float4 wv = sw4[idx];
        acc += tanh_fast(e.x + dv.x) * wv.x;
        acc += tanh_fast(e.y + dv.y) * wv.y;
        acc += tanh_fast(e.z + dv.z) * wv.z;
        acc += tanh_fast(e.w + dv.w) * wv.w;
    }
#pragma unroll
    for (int o = 16; o; o >>= 1) acc += __shfl_xor_sync(0xffffffffu, acc, o);
    if (!lane) lg[b * S + s] = acc;
}

// ---------------- k3: masked softmax over S -> attn (also zero context acc) ----------------
__global__ void k3_softmax_attn(const float* __restrict__ lg, const int* __restrict__ src,
                                float* __restrict__ attn, float* __restrict__ ctx0) {
    __shared__ float red[1024];
    int b = blockIdx.x, t = threadIdx.x;
    ctx0[b * TWOD + t] = 0.f;
    float l = lg[b * S + t];
    red[t] = l; __syncthreads();
    for (int o = 512; o; o >>= 1) { if (t < o) red[t] = fmaxf(red[t], red[t + o]); __syncthreads(); }
    float m = red[0]; __syncthreads();
    float e = __expf(l - m);
    float me = (src[b * S + t] != 0) ? e : 0.f;
    red[t] = me; __syncthreads();
    for (int o = 512; o; o >>= 1) { if (t < o) red[t] += red[t + o]; __syncthreads(); }
    attn[b * S + t] = me / red[0];
}

// ---------------- k4: context = attn @ enc_op (float4 + f32x2, split-s atomic) ----------------
// grid (B, S/64), 256 threads; each thread owns 4 contiguous d
__global__ void k4_context(const float* __restrict__ attn, const float* __restrict__ enc,
                           float* __restrict__ ctx) {
    __shared__ float sa[64];
    int b = blockIdx.x;
    int s0 = blockIdx.y * 64;
    if (threadIdx.x < 64) sa[threadIdx.x] = attn[b * S + s0 + threadIdx.x];
    __syncthreads();
    const ulonglong2* ep = (const ulonglong2*)(enc + ((size_t)(b * S + s0)) * TWOD) + threadIdx.x;
    unsigned long long acc0 = 0, acc1 = 0;  // f32x2 zero pairs
#pragma unroll 8
    for (int s = 0; s < 64; s++) {
        unsigned long long a2; DUP2(a2, sa[s]);
        ulonglong2 e = ep[s * (TWOD / 4)];
        FMA2(acc0, e.x, a2);
        FMA2(acc1, e.y, a2);
    }
    float x0, x1, x2, x3;
    UNPK2(x0, x1, acc0); UNPK2(x2, x3, acc1);
    float* cp = &ctx[b * TWOD + threadIdx.x * 4];
    atomicAdd(cp + 0, x0); atomicAdd(cp + 1, x1);
    atomicAdd(cp + 2, x2); atomicAdd(cp + 3, x3);
}

// ---------------- k5a: batchnorm -> context output ----------------
__global__ void k5_bn(const float* __restrict__ ctx, const float* __restrict__ gmean,
                      const float* __restrict__ gvar, const float* __restrict__ gamma,
                      const float* __restrict__ beta, float* __restrict__ ctxn) {
    int i = blockIdx.x * 256 + threadIdx.x;
    int j = i & 1023;
    ctxn[i] = (ctx[i] - gmean[j]) * rsqrtf(gvar[j] + BN_EPS) * gamma[j] + beta[j];
}

// ---------------- k5b: p_gen ----------------
__global__ void k5_pgen(const float* __restrict__ ctxn, const float* __restrict__ h,
                        const float* __restrict__ c, const float* __restrict__ dinp,
                        const float* __restrict__ Wp, const float* __restrict__ bp,
                        float* __restrict__ pg) {
    __shared__ float red[256];
    int b = blockIdx.x, t = threadIdx.x;
    float acc = 0.f;
    for (int k = t; k < 5 * D; k += 256) {
        float x;
        if (k < 1024)       x = ctxn[b * TWOD + k];
        else if (k < 1536)  x = h[b * D + k - 1024];
        else if (k < 2048)  x = c[b * D + k - 1536];
        else                x = dinp[b * D + k - 2048];
        acc += Wp[k] * x;
    }
    red[t] = acc; __syncthreads();
    for (int o = 128; o; o >>= 1) { if (t < o) red[t] += red[t + o]; __syncthreads(); }
    if (!t) pg[b] = 1.f / (1.f + __expf(-(red[0] + bp[0])));
}

// ---------------- k5c: hidden = [dec_output; ctxn] @ W_v1^T + b_v1 ----------------
__global__ void k5_hidden(const float* __restrict__ dec_out, const float* __restrict__ ctxn,
                          const float* __restrict__ W1, const float* __restrict__ b1,
                          float* __restrict__ hid) {
    int gw = (blockIdx.x * blockDim.x + threadIdx.x) >> 5;
    int lane = threadIdx.x & 31;
    int b = gw >> 9, j = gw & 511;
    const float* wr = W1 + (size_t)j * (3 * D);
    float acc = 0.f;
#pragma unroll 8
    for (int k = lane; k < 3 * D; k += 32) {
        float x = (k < D) ? dec_out[b * D + k] : ctxn[b * TWOD + k - D];
        acc += x * wr[k];
    }
#pragma unroll
    for (int o = 16; o; o >>= 1) acc += __shfl_xor_sync(0xffffffffu, acc, o);
    if (!lane) hid[b * D + j] = acc + b1[j];
}

// ---------------- k6: logits = hidden @ W_v2^T + b_v2  (FFMA2 path) ----------------
__global__ void k6_vocab(const float* __restrict__ hidden, const float* __restrict__ W2,
                         const float* __restrict__ b2, float* __restrict__ lg) {
    extern __shared__ float sm[];
    float* sh = sm;              // [512][32] -> sh[k*32+b]
    float* swt = sm + D * B;     // [256][17]
    int tid = threadIdx.x;
    for (int i = tid; i < D * B; i += 256) {
        int bb = i >> 9, k = i & 511;
        sh[k * 32 + bb] = hidden[i];
    }
    int v0 = blockIdx.x * 256;
    int v = v0 + tid;
    unsigned long long acc2[16];
#pragma unroll
    for (int q = 0; q < 16; q++) acc2[q] = 0ull;
    float bias = (v < NV) ? b2[v] : 0.f;

    for (int kt = 0; kt < D; kt += 16) {
        __syncthreads();
#pragma unroll
        for (int j = 0; j < 16; j++) {
            int idx = j * 256 + tid;
            int r = idx >> 4, k = idx & 15;
            int vr = v0 + r;
            swt[r * 17 + k] = (vr < NV) ? W2[(size_t)vr * D + kt + k] : 0.f;
        }
        __syncthreads();
#pragma unroll
        for (int k = 0; k < 16; k++) {
            float w = swt[tid * 17 + k];
            unsigned long long ww; DUP2(ww, w);
            const ulonglong2* h2 = (const ulonglong2*)&sh[(kt + k) * 32];
#pragma unroll
            for (int q = 0; q < 8; q++) {
                ulonglong2 hv = h2[q];
                FMA2(acc2[q * 2 + 0], hv.x, ww);
                FMA2(acc2[q * 2 + 1], hv.y, ww);
            }
        }
    }
    if (v < NV) {
#pragma unroll
        for (int q = 0; q < 16; q++) {
            float lo, hi; UNPK2(lo, hi, acc2[q]);
            lg[(size_t)(q * 2 + 0) * NV + v] = lo + bias;
            lg[(size_t)(q * 2 + 1) * NV + v] = hi + bias;
        }
    }
}

// ---------------- k7a: per-chunk max & sumexp over logits ----------------
// grid (NCHUNK, B), 256 threads; chunk = 1024 elems
__global__ void k7a_partial(const float* __restrict__ lg, float* __restrict__ pmax,
                            float* __restrict__ psum) {
    __shared__ float red[256];
    int b = blockIdx.y, ch = blockIdx.x, t = threadIdx.x;
    const float* lr = lg + (size_t)b * NV + ch * 1024;
    int lim = NV - ch * 1024; if (lim > 1024) lim = 1024;
    float m = -1e30f;
#pragma unroll
    for (int i = 0; i < 4; i++) {
        int v = t + i * 256;
        if (v < lim) m = fmaxf(m, lr[v]);
    }
    red[t] = m; __syncthreads();
    for (int o = 128; o; o >>= 1) { if (t < o) red[t] = fmaxf(red[t], red[t + o]); __syncthreads(); }
    m = red[0]; __syncthreads();
    float s = 0.f;
#pragma unroll
    for (int i = 0; i < 4; i++) {
        int v = t + i * 256;
        if (v < lim) s += __expf(lr[v] - m);
    }
    red[t] = s; __syncthreads();
    for (int o = 128; o; o >>= 1) { if (t < o) red[t] += red[t + o]; __syncthreads(); }
    if (!t) { pmax[b * NCHUNK + ch] = m; psum[b * NCHUNK + ch] = red[0]; }
}

// ---------------- k7b: combine partials -> scale, gmax ----------------
__global__ void k7b_combine(const float* __restrict__ pmax, const float* __restrict__ psum,
                            const float* __restrict__ pg, float* __restrict__ scale,
                            float* __restrict__ gmax) {
    __shared__ float rm[64], rs[64];
    int b = blockIdx.x, t = threadIdx.x;
    float m = (t < NCHUNK) ? pmax[b * NCHUNK + t] : -1e30f;
    rm[t] = m; __syncthreads();
    for (int o = 32; o; o >>= 1) { if (t < o) rm[t] = fmaxf(rm[t], rm[t + o]); __syncthreads(); }
    float M = rm[0]; __syncthreads();
    float s = (t < NCHUNK) ? psum[b * NCHUNK + t] * __expf(m - M) : 0.f;
    rs[t] = s; __syncthreads();
    for (int o = 32; o; o >>= 1) { if (t < o) rs[t] += rs[t + o]; __syncthreads(); }
    if (!t) { scale[b] = pg[b] / rs[0]; gmax[b] = M; }
}

// ---------------- k7c: p_final = scale*exp(lr - gmax) (eps folded); tail = 1e-12 ----------------
__global__ void k7c_write(const float* __restrict__ lg, const float* __restrict__ scale,
                          const float* __restrict__ gmax, float* __restrict__ pf) {
    int i = blockIdx.x * 256 + threadIdx.x;
    if (i >= B * VFULL) return;
    int b = i / VFULL;
    int v = i - b * VFULL;
    float o;
    if (v < NV) {
        float val = scale[b] * __expf(lg[(size_t)b * NV + v] - gmax[b]);
        o = (val == 0.f) ? 1e-12f : val;
    } else {
        o = 1e-12f;
    }
    pf[i] = o;
}

// ---------------- k8: scatter-add (1-p_gen)*attn at src indices ----------------
__global__ void k8_scatter(const float* __restrict__ attn, const float* __restrict__ pg,
                           const int* __restrict__ src, float* __restrict__ pf) {
    int i = blockIdx.x * 256 + threadIdx.x;
    int b = i >> 10;
    float w = (1.f - pg[b]) * attn[i];
    atomicAdd(&pf[(size_t)b * VFULL + src[i]], w);
}

extern "C" void kernel_launch(void* const* d_in, const int* in_sizes, int n_in,
                              void* d_out, int out_size) {
    const float* dec_output = (const float*)d_in[0];
    const float* h          = (const float*)d_in[1];
    const float* c          = (const float*)d_in[2];
    const float* dec_inp    = (const float*)d_in[3];
    const float* enc_op     = (const float*)d_in[4];
    const float* enc_op1    = (const float*)d_in[5];
    const int*   src        = (const int*)d_in[6];
    const float* W_dec      = (const float*)d_in[7];
    const float* b_dec      = (const float*)d_in[8];
    const float* w_attn     = (const float*)d_in[9];
    const float* W_v1       = (const float*)d_in[10];
    const float* b_v1       = (const float*)d_in[11];
    const float* W_v2       = (const float*)d_in[12];
    const float* b_v2       = (const float*)d_in[13];
    const float* W_p        = (const float*)d_in[14];
    const float* b_p        = (const float*)d_in[15];
    const float* bn_gamma   = (const float*)d_in[16];
    const float* bn_beta    = (const float*)d_in[17];
    const float* bn_mean    = (const float*)d_in[18];
    const float* bn_var     = (const float*)d_in[19];

    float* out = (float*)d_out;
    float* pf       = out;
    float* attn_out = out + (size_t)B * VFULL;
    float* ctx_out  = attn_out + (size_t)B * S;

    float *dec1, *alog, *ctx, *hid, *pg, *vlog, *pmax, *psum, *scale, *gmax;
    cudaGetSymbolAddress((void**)&dec1, g_dec_op1);
    cudaGetSymbolAddress((void**)&alog, g_attn_logits);
    cudaGetSymbolAddress((void**)&ctx,  g_context);
    cudaGetSymbolAddress((void**)&hid,  g_hidden);
    cudaGetSymbolAddress((void**)&pg,   g_pgen);
    cudaGetSymbolAddress((void**)&vlog, g_logits);
    cudaGetSymbolAddress((void**)&pmax, g_pmax);
    cudaGetSymbolAddress((void**)&psum, g_psum);
    cudaGetSymbolAddress((void**)&scale, g_scale);
    cudaGetSymbolAddress((void**)&gmax, g_gmax);

    static bool attr_done = false;
    if (!attr_done) {
        cudaFuncSetAttribute(k6_vocab, cudaFuncAttributeMaxDynamicSharedMemorySize,
                             (D * B + 256 * 17) * (int)sizeof(float));
        attr_done = true;
    }

    k1_decop1<<<(B * TWOD) / 8, 256>>>(h, c, W_dec, b_dec, dec1);
    k2_attnlogits<<<dim3(S / 8, B), 256>>>(enc_op1, dec1, w_attn, alog);
    k3_softmax_attn<<<B, 1024>>>(alog, src, attn_out, ctx);
    k4_context<<<dim3(B, S / 64), 256>>>(attn_out, enc_op, ctx);
    k5_bn<<<(B * TWOD) / 256, 256>>>(ctx, bn_mean, bn_var, bn_gamma, bn_beta, ctx_out);
    k5_pgen<<<B, 256>>>(ctx_out, h, c, dec_inp, W_p, b_p, pg);
    k5_hidden<<<(B * D) / 8, 256>>>(dec_output, ctx_out, W_v1, b_v1, hid);
    k6_vocab<<<(NV + 255) / 256, 256, (D * B + 256 * 17) * (int)sizeof(float)>>>(hid, W_v2, b_v2, vlog);
    k7a_partial<<<dim3(NCHUNK, B), 256>>>(vlog, pmax, psum);
    k7b_combine<<<B, 64>>>(pmax, psum, pg, scale, gmax);
    k7c_write<<<(B * VFULL + 255) / 256, 256>>>(vlog, scale, gmax, pf);
    k8_scatter<<<(B * S) / 256, 256>>>(attn_out, pg, src, pf);
}